// round 16
// baseline (speedup 1.0000x reference)
#include <cuda_runtime.h>
#include <cuda_bf16.h>
#include <math.h>
#include <stdint.h>

#define T_TOK 8192
#define HIDDEN 2048
#define NH 16
#define NKV 4
#define HD 128
#define BATCH 8
#define SEQ 1024

#define BM 128
#define BN 64
#define BK 32
#define NCH (HIDDEN / BK)          // 64
#define ROWBLKS (T_TOK / BM)
#define NQKV 3072

// smem tiles: A 128x32bf16 = 8KB (hi+lo), B 64x32bf16 = 4KB (hi+lo)
#define T32 8192
#define STG32 24576
#define GSMEM32 (3 * STG32)        // 73728 -> 2 CTAs/SM

// 64B-row swizzle (conflict-free for LDSM and stores)
#define SWZ(row, c) (((uint32_t)(row)) * 64 + ((((c) ^ (((row) >> 1) & 3))) << 4))

// -------- scratch --------
__device__ float g_q[(size_t)T_TOK * NH * HD];
__device__ float g_k[(size_t)T_TOK * NKV * HD];
__device__ float g_o[(size_t)T_TOK * NH * HD];   // reused as bf16 hi/lo planes
__device__ int   g_perm[T_TOK];
__device__ int   g_iperm[T_TOK];
__device__ int   g_n0;

__device__ __nv_bfloat16 g_xh[(size_t)T_TOK * HIDDEN];
__device__ __nv_bfloat16 g_xl[(size_t)T_TOK * HIDDEN];
__device__ __nv_bfloat16 g_kh[(size_t)T_TOK * NKV * HD];
__device__ __nv_bfloat16 g_kl[(size_t)T_TOK * NKV * HD];
__device__ __nv_bfloat16 g_vh[(size_t)T_TOK * NKV * HD];
__device__ __nv_bfloat16 g_vl[(size_t)T_TOK * NKV * HD];
#define WROWS (2 * NQKV + 2 * 2048)
__device__ __nv_bfloat16 g_wh[(size_t)WROWS * 2048];
__device__ __nv_bfloat16 g_wl[(size_t)WROWS * 2048];

// -------- asm helpers --------
__device__ __forceinline__ uint32_t smem_to_u32(const void* p) {
    uint32_t a;
    asm("{ .reg .u64 t; cvta.to.shared.u64 t, %1; cvt.u32.u64 %0, t; }"
        : "=r"(a) : "l"(p));
    return a;
}
#define CPA(dst, src) asm volatile( \
    "cp.async.cg.shared.global [%0], [%1], 16;" \
    :: "r"(dst), "l"(src) : "memory")
#define CPC() asm volatile("cp.async.commit_group;" ::: "memory")
#define CPW(n) asm volatile("cp.async.wait_group %0;" :: "n"(n) : "memory")

#define LDSM4(r, a) asm volatile( \
    "ldmatrix.sync.aligned.m8n8.x4.shared.b16 {%0,%1,%2,%3}, [%4];" \
    : "=r"((r)[0]), "=r"((r)[1]), "=r"((r)[2]), "=r"((r)[3]) : "r"(a))
#define LDSM4T(r, a) asm volatile( \
    "ldmatrix.sync.aligned.m8n8.x4.trans.shared.b16 {%0,%1,%2,%3}, [%4];" \
    : "=r"((r)[0]), "=r"((r)[1]), "=r"((r)[2]), "=r"((r)[3]) : "r"(a))

#define MMA_BF16(d, a, b0, b1) asm volatile( \
    "mma.sync.aligned.m16n8k16.row.col.f32.bf16.bf16.f32 " \
    "{%0,%1,%2,%3}, {%4,%5,%6,%7}, {%8,%9}, {%0,%1,%2,%3};" \
    : "+f"((d)[0]), "+f"((d)[1]), "+f"((d)[2]), "+f"((d)[3]) \
    : "r"((a)[0]), "r"((a)[1]), "r"((a)[2]), "r"((a)[3]), "r"(b0), "r"(b1))

// -------- partition --------
__global__ void partition_kernel(const int* __restrict__ gm) {
    __shared__ int sc[1024];
    int tid = threadIdx.x, base = tid * 8, z = 0;
#pragma unroll
    for (int i = 0; i < 8; i++) z += (gm[base + i] > 0) ? 0 : 1;
    sc[tid] = z;
    __syncthreads();
    for (int off = 1; off < 1024; off <<= 1) {
        int v = (tid >= off) ? sc[tid - off] : 0;
        __syncthreads();
        sc[tid] += v;
        __syncthreads();
    }
    int total0 = sc[1023], zpos = sc[tid] - z, opos = base - zpos;
#pragma unroll
    for (int i = 0; i < 8; i++) {
        int t = base + i;
        if (gm[t] > 0) {
            int p = total0 + opos++;
            g_perm[p] = t;
            g_iperm[t] = p;
        } else {
            int p = zpos++;
            g_perm[p] = t;
            g_iperm[t] = p;
        }
    }
    if (tid == 0) g_n0 = total0;
}

// -------- fp32 -> bf16 hi/lo split --------
__device__ __forceinline__ void split4(float4 v, uint2& H, uint2& L) {
    __nv_bfloat16 h0 = __float2bfloat16(v.x), h1 = __float2bfloat16(v.y);
    __nv_bfloat16 h2 = __float2bfloat16(v.z), h3 = __float2bfloat16(v.w);
    __nv_bfloat16 l0 = __float2bfloat16(v.x - __bfloat162float(h0));
    __nv_bfloat16 l1 = __float2bfloat16(v.y - __bfloat162float(h1));
    __nv_bfloat16 l2 = __float2bfloat16(v.z - __bfloat162float(h2));
    __nv_bfloat16 l3 = __float2bfloat16(v.w - __bfloat162float(h3));
    H.x = ((uint32_t)__bfloat16_as_ushort(h1) << 16) | __bfloat16_as_ushort(h0);
    H.y = ((uint32_t)__bfloat16_as_ushort(h3) << 16) | __bfloat16_as_ushort(h2);
    L.x = ((uint32_t)__bfloat16_as_ushort(l1) << 16) | __bfloat16_as_ushort(l0);
    L.y = ((uint32_t)__bfloat16_as_ushort(l3) << 16) | __bfloat16_as_ushort(l2);
}
__device__ __forceinline__ uint32_t packsplit2(float x, float y, uint32_t& lo) {
    __nv_bfloat16 hx = __float2bfloat16(x), hy = __float2bfloat16(y);
    __nv_bfloat16 lx = __float2bfloat16(x - __bfloat162float(hx));
    __nv_bfloat16 ly = __float2bfloat16(y - __bfloat162float(hy));
    lo = ((uint32_t)__bfloat16_as_ushort(ly) << 16) | __bfloat16_as_ushort(lx);
    return ((uint32_t)__bfloat16_as_ushort(hy) << 16) | __bfloat16_as_ushort(hx);
}
__global__ void cvt_perm(const float* __restrict__ src,
                         __nv_bfloat16* __restrict__ hi,
                         __nv_bfloat16* __restrict__ lo) {
    int i = blockIdx.x * 256 + threadIdx.x;
    int r = i >> 9, c4 = i & 511;
    float4 v = ((const float4*)(src + (size_t)g_perm[r] * HIDDEN))[c4];
    uint2 H, L;
    split4(v, H, L);
    ((uint2*)hi)[i] = H;
    ((uint2*)lo)[i] = L;
}
__global__ void cvt_weights(const float* __restrict__ Wq_,
                            const float* __restrict__ Wk_,
                            const float* __restrict__ Wv_,
                            const float* __restrict__ Wqg_,
                            const float* __restrict__ Wkg_,
                            const float* __restrict__ Wvg_,
                            const float* __restrict__ Wo_,
                            const float* __restrict__ Wog_) {
    int i = blockIdx.x * 256 + threadIdx.x;
    int r = i >> 9, c4 = i & 511;
    const float* src;
    if (r < 2048)       src = Wq_  + (size_t)r * 2048;
    else if (r < 2560)  src = Wk_  + (size_t)(r - 2048) * 2048;
    else if (r < 3072)  src = Wv_  + (size_t)(r - 2560) * 2048;
    else if (r < 5120)  src = Wqg_ + (size_t)(r - 3072) * 2048;
    else if (r < 5632)  src = Wkg_ + (size_t)(r - 5120) * 2048;
    else if (r < 6144)  src = Wvg_ + (size_t)(r - 5632) * 2048;
    else if (r < 8192)  src = Wo_  + (size_t)(r - 6144) * 2048;
    else                src = Wog_ + (size_t)(r - 8192) * 2048;
    float4 v = ((const float4*)src)[c4];
    uint2 H, L;
    split4(v, H, L);
    ((uint2*)g_wh)[i] = H;
    ((uint2*)g_wl)[i] = L;
}

// =================================================================
// bf16 GEMM mainloop: CTA 128x64, BK=32, warp 32x32 (4m x 2n),
// 3-stage cp.async, 2 CTAs/SM
// =================================================================
#define GEMM_MAIN(AghP, AglP, BhP, BlP)                                    \
    float acc[2][4][4];                                                    \
    _Pragma("unroll")                                                      \
    for (int a = 0; a < 2; a++)                                            \
        _Pragma("unroll")                                                  \
        for (int b = 0; b < 4; b++)                                        \
            _Pragma("unroll")                                              \
            for (int c = 0; c < 4; c++) acc[a][b][c] = 0.0f;               \
    const int tid = threadIdx.x, wid = tid >> 5, lane = tid & 31;          \
    const int mbase = (wid & 3) * 32;                                      \
    const int nbase = (wid >> 2) * 32;                                     \
    extern __shared__ char smem[];                                         \
    const uint32_t sb = smem_to_u32(smem);                                 \
    const int ldrow = tid >> 2, ldc = tid & 3;                             \
    auto load_stage = [&](int st, int ch_) {                               \
        uint32_t base_ = sb + st * STG32;                                  \
        int k0 = ch_ * BK;                                                 \
        _Pragma("unroll")                                                  \
        for (int it = 0; it < 2; it++) {                                   \
            int row = ldrow + it * 64;                                     \
            uint32_t d = base_ + SWZ(row, ldc);                            \
            size_t ga = (size_t)(row0 + row) * HIDDEN + k0 + ldc * 8;      \
            CPA(d,       AghP + ga);                                       \
            CPA(d + T32, AglP + ga);                                       \
        }                                                                  \
        {                                                                  \
            uint32_t d = base_ + 16384 + SWZ(ldrow, ldc);                  \
            size_t gb = (size_t)(col0 + ldrow) * HIDDEN + k0 + ldc * 8;    \
            CPA(d,        BhP + gb);                                       \
            CPA(d + 4096, BlP + gb);                                       \
        }                                                                  \
        CPC();                                                             \
    };                                                                     \
    load_stage(0, 0);                                                      \
    load_stage(1, 1);                                                      \
    const int q_ = lane >> 3, rr = lane & 7;                               \
    const int arow_off = (q_ & 1) * 8 + rr;                                \
    const int achk_off = (q_ >> 1);                                        \
    const int brow_off = (q_ >> 1) * 8 + rr;                               \
    const int bchk_off = (q_ & 1);                                         \
    for (int ch = 0; ch < NCH; ch++) {                                     \
        if (ch == NCH - 1) CPW(0); else CPW(1);                            \
        __syncthreads();                                                   \
        if (ch + 2 < NCH) load_stage((ch + 2) % 3, ch + 2);                \
        const uint32_t so = sb + (ch % 3) * STG32;                         \
        _Pragma("unroll")                                                  \
        for (int ks = 0; ks < 2; ks++) {                                   \
            uint32_t bh[2][4], bl[2][4];                                   \
            _Pragma("unroll")                                              \
            for (int nb = 0; nb < 2; nb++) {                               \
                int row = nbase + nb * 16 + brow_off;                      \
                int chk = ks * 2 + bchk_off;                               \
                uint32_t bd = so + 16384 + SWZ(row, chk);                  \
                LDSM4(bh[nb], bd);                                         \
                LDSM4(bl[nb], bd + 4096);                                  \
            }                                                              \
            _Pragma("unroll")                                              \
            for (int mt = 0; mt < 2; mt++) {                               \
                uint32_t ah4[4], al4[4];                                   \
                int row = mbase + mt * 16 + arow_off;                      \
                int chk = ks * 2 + achk_off;                               \
                uint32_t ad = so + SWZ(row, chk);                          \
                LDSM4(ah4, ad);                                            \
                LDSM4(al4, ad + T32);                                      \
                _Pragma("unroll")                                          \
                for (int nt = 0; nt < 4; nt++) {                           \
                    int nb = nt >> 1, i0 = (nt & 1) * 2;                   \
                    MMA_BF16(acc[mt][nt], ah4, bh[nb][i0], bh[nb][i0+1]);  \
                    MMA_BF16(acc[mt][nt], ah4, bl[nb][i0], bl[nb][i0+1]);  \
                    MMA_BF16(acc[mt][nt], al4, bh[nb][i0], bh[nb][i0+1]);  \
                }                                                          \
            }                                                              \
        }                                                                  \
    }

__device__ __forceinline__ bool route_setup(int by, int n0,
                                            int& rowblk, int& wlo, int& whi,
                                            bool& useW1) {
    if (by < ROWBLKS) {
        rowblk = by;
        int lo = rowblk * BM, hi2 = lo + BM;
        if (hi2 <= n0)     { useW1 = false; wlo = lo; whi = hi2; }
        else if (lo >= n0) { useW1 = true;  wlo = lo; whi = hi2; }
        else               { useW1 = false; wlo = lo; whi = n0;  }
        return true;
    }
    if ((n0 & (BM - 1)) == 0) return false;
    rowblk = n0 / BM; useW1 = true; wlo = n0; whi = rowblk * BM + BM;
    return true;
}

// =================================================================
// merged QKV GEMM: segmented epilogue
// =================================================================
__global__ __launch_bounds__(256, 2)
void gemm_qkv(const __nv_bfloat16* __restrict__ Agh,
              const __nv_bfloat16* __restrict__ Agl,
              const float* __restrict__ bq, const float* __restrict__ bqg,
              const float* __restrict__ bk, const float* __restrict__ bkg,
              const float* __restrict__ bv, const float* __restrict__ bvg,
              float* __restrict__ Cq, float* __restrict__ Ck,
              __nv_bfloat16* __restrict__ Vh, __nv_bfloat16* __restrict__ Vl) {
    const int n0 = g_n0;
    int rowblk, wlo, whi;
    bool useW1;
    if (!route_setup(blockIdx.y, n0, rowblk, wlo, whi, useW1)) return;
    const int row0 = rowblk * BM;
    const int col0 = blockIdx.x * BN;
    const __nv_bfloat16* __restrict__ Bh = g_wh + (useW1 ? (size_t)NQKV * 2048 : 0);
    const __nv_bfloat16* __restrict__ Bl = g_wl + (useW1 ? (size_t)NQKV * 2048 : 0);

    GEMM_MAIN(Agh, Agl, Bh, Bl)

    const int seg = (col0 < 2048) ? 0 : (col0 < 2560 ? 1 : 2);
    const float* bias;
    int cbase, Nout;
    if (seg == 0)      { bias = useW1 ? bqg : bq; cbase = col0;        Nout = 2048; }
    else if (seg == 1) { bias = useW1 ? bkg : bk; cbase = col0 - 2048; Nout = 512; }
    else               { bias = useW1 ? bvg : bv; cbase = col0 - 2560; Nout = 512; }

#pragma unroll
    for (int mt = 0; mt < 2; mt++) {
        int r0 = row0 + mbase + mt * 16 + (lane >> 2);
        int r1 = r0 + 8;
        bool w0 = (r0 >= wlo) && (r0 < whi);
        bool w1 = (r1 >= wlo) && (r1 < whi);
        int tok0 = w0 ? g_perm[r0] : 0;
        int tok1 = w1 ? g_perm[r1] : 0;
#pragma unroll
        for (int nt = 0; nt < 4; nt++) {
            int colL = cbase + nbase + nt * 8 + (lane & 3) * 2;
            float b0f = bias[colL], b1f = bias[colL + 1];
            float v00 = acc[mt][nt][0] + b0f, v01 = acc[mt][nt][1] + b1f;
            float v10 = acc[mt][nt][2] + b0f, v11 = acc[mt][nt][3] + b1f;
            if (seg < 2) {
                float* C = (seg == 0) ? Cq : Ck;
                if (w0) *(float2*)(C + (size_t)tok0 * Nout + colL) = make_float2(v00, v01);
                if (w1) *(float2*)(C + (size_t)tok1 * Nout + colL) = make_float2(v10, v11);
            } else {
                if (w0) {
                    uint32_t lo_, hi_ = packsplit2(v00, v01, lo_);
                    *(uint32_t*)((uint16_t*)Vh + (size_t)tok0 * 512 + colL) = hi_;
                    *(uint32_t*)((uint16_t*)Vl + (size_t)tok0 * 512 + colL) = lo_;
                }
                if (w1) {
                    uint32_t lo_, hi_ = packsplit2(v10, v11, lo_);
                    *(uint32_t*)((uint16_t*)Vh + (size_t)tok1 * 512 + colL) = hi_;
                    *(uint32_t*)((uint16_t*)Vl + (size_t)tok1 * 512 + colL) = lo_;
                }
            }
        }
    }
}

// =================================================================
// O-projection GEMM -> fp32 out, no bias
// =================================================================
__global__ __launch_bounds__(256, 2)
void gemm_o(const __nv_bfloat16* __restrict__ Agh,
            const __nv_bfloat16* __restrict__ Agl,
            float* __restrict__ C) {
    const int n0 = g_n0;
    int rowblk, wlo, whi;
    bool useW1;
    if (!route_setup(blockIdx.y, n0, rowblk, wlo, whi, useW1)) return;
    const int row0 = rowblk * BM;
    const int col0 = blockIdx.x * BN;
    const size_t wbase = (size_t)(2 * NQKV) * 2048 +
                         (useW1 ? (size_t)2048 * 2048 : 0);
    const __nv_bfloat16* __restrict__ Bh = g_wh + wbase;
    const __nv_bfloat16* __restrict__ Bl = g_wl + wbase;

    GEMM_MAIN(Agh, Agl, Bh, Bl)

#pragma unroll
    for (int mt = 0; mt < 2; mt++) {
        int r0 = row0 + mbase + mt * 16 + (lane >> 2);
        int r1 = r0 + 8;
        bool w0 = (r0 >= wlo) && (r0 < whi);
        bool w1 = (r1 >= wlo) && (r1 < whi);
        int tok0 = w0 ? g_perm[r0] : 0;
        int tok1 = w1 ? g_perm[r1] : 0;
#pragma unroll
        for (int nt = 0; nt < 4; nt++) {
            int colg = col0 + nbase + nt * 8 + (lane & 3) * 2;
            if (w0)
                *(float2*)(C + (size_t)tok0 * HIDDEN + colg) =
                    make_float2(acc[mt][nt][0], acc[mt][nt][1]);
            if (w1)
                *(float2*)(C + (size_t)tok1 * HIDDEN + colg) =
                    make_float2(acc[mt][nt][2], acc[mt][nt][3]);
        }
    }
}

// =================================================================
// RMS norm + RoPE; emits bf16 hi/lo (Q pre-scaled by 1/sqrt(D))
// =================================================================
__global__ void rmsrope_kernel(const int* __restrict__ gm,
                               const float* __restrict__ cosb,
                               const float* __restrict__ sinb,
                               const float* __restrict__ qw,
                               const float* __restrict__ qwg,
                               const float* __restrict__ kw,
                               const float* __restrict__ kwg) {
    const int warp = (blockIdx.x * blockDim.x + threadIdx.x) >> 5;
    const int lane = threadIdx.x & 31;
    const int QP = T_TOK * NH;
    if (warp >= QP + T_TOK * NKV) return;
    const float* src;
    __nv_bfloat16 *dh, *dl;
    const float* w;
    int t;
    float oscale;
    if (warp < QP) {
        t = warp >> 4;
        src = g_q + (size_t)warp * HD;
        dh = g_xh + (size_t)warp * HD;
        dl = g_xl + (size_t)warp * HD;
        w = (gm[t] > 0) ? qwg : qw;
        oscale = 0.08838834764831845f;
    } else {
        int p = warp - QP;
        t = p >> 2;
        src = g_k + (size_t)p * HD;
        dh = g_kh + (size_t)p * HD;
        dl = g_kl + (size_t)p * HD;
        w = (gm[t] > 0) ? kwg : kw;
        oscale = 1.0f;
    }
    float v[4];
#pragma unroll
    for (int r = 0; r < 4; r++) v[r] = src[lane + 32 * r];
    float ss = v[0]*v[0] + v[1]*v[1] + v[2]*v[2] + v[3]*v[3];
#pragma unroll
    for (int off = 16; off > 0; off >>= 1)
        ss += __shfl_xor_sync(0xffffffffu, ss, off);
    float rs = rsqrtf(ss * (1.0f / 128.0f) + 1e-6f);
#pragma unroll
    for (int r = 0; r < 4; r++) v[r] = v[r] * rs * w[lane + 32 * r];
    float rot[4] = {-v[2], -v[3], v[0], v[1]};
#pragma unroll
    for (int r = 0; r < 4; r++) {
        int d = lane + 32 * r;
        float c = cosb[(size_t)t * HD + d];
        float s = sinb[(size_t)t * HD + d];
        float val = (v[r] * c + rot[r] * s) * oscale;
        __nv_bfloat16 h = __float2bfloat16(val);
        __nv_bfloat16 l = __float2bfloat16(val - __bfloat162float(h));
        dh[d] = h;
        dl[d] = l;
    }
}

// =================================================================
// FA2 attention (bf16 3-term), LPT grid, fused permuted bf16 epilogue
// =================================================================
#define A_RGN 65536
#define A_SMEM (3 * A_RGN)

__device__ __forceinline__ void load_kv_stage(
    uint32_t rgn, int tid,
    const __nv_bfloat16* __restrict__ kh, const __nv_bfloat16* __restrict__ kl,
    const __nv_bfloat16* __restrict__ vh, const __nv_bfloat16* __restrict__ vl,
    size_t gbase) {
#pragma unroll
    for (int i = 0; i < 4; i++) {
        int idx = tid + (i << 8);
        int row = idx >> 4, c = idx & 15;
        uint32_t d = rgn + row * 256 + ((c ^ (row & 7)) << 4);
        size_t g = gbase + (size_t)row * 512 + c * 8;
        CPA(d,          kh + g);
        CPA(d + 16384,  kl + g);
        CPA(d + 32768,  vh + g);
        CPA(d + 49152,  vl + g);
    }
    CPC();
}

__global__ __launch_bounds__(256, 1)
void attn_mma(const __nv_bfloat16* __restrict__ qh,
              const __nv_bfloat16* __restrict__ ql,
              const __nv_bfloat16* __restrict__ kh,
              const __nv_bfloat16* __restrict__ kl,
              const __nv_bfloat16* __restrict__ vh,
              const __nv_bfloat16* __restrict__ vl,
              __nv_bfloat16* __restrict__ oh,
              __nv_bfloat16* __restrict__ ol) {
    extern __shared__ char smem[];
    const uint32_t sb = smem_to_u32(smem);
    const int tid = threadIdx.x, wid = tid >> 5, lane = tid & 31;
    const int bid = blockIdx.x;
    const int qb = (SEQ / 128 - 1) - (bid >> 7);
    const int hb = bid & 127;
    const int h = hb & 15;
    const int b = hb >> 4;
    const int kvh = h >> 2;
    const int q0 = qb * 128;
    const size_t qgbase = ((size_t)(b * SEQ + q0)) * 2048 + h * 128;
    const size_t kvgbase = ((size_t)(b * SEQ)) * 512 + kvh * 128;
    const int nkb = 2 * qb + 2;

#pragma unroll
    for (int i = 0; i < 8; i++) {
        int idx = tid + (i << 8);
        int row = idx >> 4, c = idx & 15;
        uint32_t d = sb + row * 256 + ((c ^ (row & 7)) << 4);
        size_t g = qgbase + (size_t)row * 2048 + c * 8;
        CPA(d, qh + g);
        CPA(d + 32768, ql + g);
    }
    CPC();
    load_kv_stage(sb + A_RGN, tid, kh, kl, vh, vl, kvgbase);
    CPW(1);
    __syncthreads();

    const int rr = lane & 7;
    const int arow = wid * 16 + ((lane >> 3) & 1) * 8 + rr;
    const int acb = lane >> 4;
    uint32_t Qh4[8][4], Ql4[8][4];
#pragma unroll
    for (int kk = 0; kk < 8; kk++) {
        int ck = kk * 2 + acb;
        uint32_t ad = sb + arow * 256 + ((ck ^ (arow & 7)) << 4);
        LDSM4(Qh4[kk], ad);
        LDSM4(Ql4[kk], ad + 32768);
    }
    __syncthreads();
    if (nkb > 1)
        load_kv_stage(sb + 2 * A_RGN, tid, kh, kl, vh, vl, kvgbase + 64 * 512);

    float m0 = -1e30f, m1 = -1e30f, l0 = 0.0f, l1 = 0.0f;
    float oa[16][4];
#pragma unroll
    for (int i = 0; i < 16; i++)
#pragma unroll
        for (int j = 0; j < 4; j++) oa[i][j] = 0.0f;

    const int brow_off = ((lane >> 4) & 1) * 8 + rr;
    const int bcb = (lane >> 3) & 1;
    const int vrow_off = lane & 15;
    const int vcb = lane >> 4;
    const int rowg0 = q0 + wid * 16 + (lane >> 2);
    const int rowg1 = rowg0 + 8;
    const int warprow0 = q0 + wid * 16;

    for (int kb = 0; kb < nkb; kb++) {
        if (kb + 1 == nkb) CPW(0); else CPW(1);
        __syncthreads();
        if (kb + 2 < nkb)
            load_kv_stage(sb + ((kb + 3) % 3) * A_RGN, tid, kh, kl, vh, vl,
                          kvgbase + (size_t)(kb + 2) * 64 * 512);

        const uint32_t so = sb + ((kb + 1) % 3) * A_RGN;

        float s[8][4];
#pragma unroll
        for (int i = 0; i < 8; i++)
#pragma unroll
            for (int j = 0; j < 4; j++) s[i][j] = 0.0f;

#pragma unroll
        for (int kk = 0; kk < 8; kk++) {
#pragma unroll
            for (int p = 0; p < 4; p++) {
                int krow = p * 16 + brow_off;
                int ck = kk * 2 + bcb;
                uint32_t kd = so + krow * 256 + ((ck ^ (krow & 7)) << 4);
                uint32_t bh4[4], bl4[4];
                LDSM4(bh4, kd);
                LDSM4(bl4, kd + 16384);
                MMA_BF16(s[2*p],   Qh4[kk], bh4[0], bh4[1]);
                MMA_BF16(s[2*p],   Qh4[kk], bl4[0], bl4[1]);
                MMA_BF16(s[2*p],   Ql4[kk], bh4[0], bh4[1]);
                MMA_BF16(s[2*p+1], Qh4[kk], bh4[2], bh4[3]);
                MMA_BF16(s[2*p+1], Qh4[kk], bl4[2], bl4[3]);
                MMA_BF16(s[2*p+1], Ql4[kk], bh4[2], bh4[3]);
            }
        }

        if (kb * 64 + 63 > warprow0) {
            int colb = kb * 64 + (lane & 3) * 2;
#pragma unroll
            for (int nt = 0; nt < 8; nt++) {
                int c = colb + nt * 8;
                if (c > rowg0)     s[nt][0] = -1e30f;
                if (c + 1 > rowg0) s[nt][1] = -1e30f;
                if (c > rowg1)     s[nt][2] = -1e30f;
                if (c + 1 > rowg1) s[nt][3] = -1e30f;
            }
        }

        float mx0 = -1e30f, mx1 = -1e30f;
#pragma unroll
        for (int nt = 0; nt < 8; nt++) {
            mx0 = fmaxf(mx0, fmaxf(s[nt][0], s[nt][1]));
            mx1 = fmaxf(mx1, fmaxf(s[nt][2], s[nt][3]));
        }
        mx0 = fmaxf(mx0, __shfl_xor_sync(0xffffffffu, mx0, 1));
        mx0 = fmaxf(mx0, __shfl_xor_sync(0xffffffffu, mx0, 2));
        mx1 = fmaxf(mx1, __shfl_xor_sync(0xffffffffu, mx1, 1));
        mx1 = fmaxf(mx1, __shfl_xor_sync(0xffffffffu, mx1, 2));
        float nm0 = fmaxf(m0, mx0), nm1 = fmaxf(m1, mx1);
        float corr0 = __expf(m0 - nm0), corr1 = __expf(m1 - nm1);
        float ps0 = 0.0f, ps1 = 0.0f;
#pragma unroll
        for (int nt = 0; nt < 8; nt++) {
            s[nt][0] = __expf(s[nt][0] - nm0);
            s[nt][1] = __expf(s[nt][1] - nm0);
            s[nt][2] = __expf(s[nt][2] - nm1);
            s[nt][3] = __expf(s[nt][3] - nm1);
            ps0 += s[nt][0] + s[nt][1];
            ps1 += s[nt][2] + s[nt][3];
        }
        ps0 += __shfl_xor_sync(0xffffffffu, ps0, 1);
        ps0 += __shfl_xor_sync(0xffffffffu, ps0, 2);
        ps1 += __shfl_xor_sync(0xffffffffu, ps1, 1);
        ps1 += __shfl_xor_sync(0xffffffffu, ps1, 2);
        l0 = l0 * corr0 + ps0;
        l1 = l1 * corr1 + ps1;
        m0 = nm0; m1 = nm1;
#pragma unroll
        for (int i = 0; i < 16; i++) {
            oa[i][0] *= corr0; oa[i][1] *= corr0;
            oa[i][2] *= corr1; oa[i][3] *= corr1;
        }

#pragma unroll
        for (int kt = 0; kt < 4; kt++) {
            uint32_t ah4[4], al4[4];
            ah4[0] = packsplit2(s[2*kt][0],   s[2*kt][1],   al4[0]);
            ah4[1] = packsplit2(s[2*kt][2],   s[2*kt][3],   al4[1]);
            ah4[2] = packsplit2(s[2*kt+1][0], s[2*kt+1][1], al4[2]);
            ah4[3] = packsplit2(s[2*kt+1][2], s[2*kt+1][3], al4[3]);
#pragma unroll
            for (int dp = 0; dp < 8; dp++) {
                int vr = kt * 16 + vrow_off;
                int ck = dp * 2 + vcb;
                uint32_t vd = so + 32768 + vr * 256 + ((ck ^ (vr & 7)) << 4);
                uint32_t bh4[4], bl4[4];
                LDSM4T(bh4, vd);
                LDSM4T(bl4, vd + 16384);
                MMA_BF16(oa[2*dp],   ah4, bh4[0], bh4[1]);
                MMA_BF16(oa[2*dp],   ah4, bl4[0], bl4[1]);
                MMA_BF16(oa[2*dp],   al4, bh4[0], bh4[1]);
                MMA_BF16(oa[2*dp+1], ah4, bh4[2], bh4[3]);
                MMA_BF16(oa[2*dp+1], ah4, bl4[2], bl4[3]);
                MMA_BF16(oa[2*dp+1], al4, bh4[2], bh4[3]);
            }
        }
    }

    float inv0 = 1.0f / l0, inv1 = 1.0f / l1;
    int p0 = g_iperm[b * SEQ + rowg0];
    int p1 = g_iperm[b * SEQ + rowg1];
    size_t ob0 = (size_t)p0 * 2048 + h * 128 + (lane & 3) * 2;
    size_t ob1 = (size_t)p1 * 2048 + h * 128 + (lane & 3) * 2;
#pragma unroll
    for (int nt = 0; nt < 16; nt++) {
        uint32_t lo0, hi0 = packsplit2(oa[nt][0] * inv0, oa[nt][1] * inv0, lo0);
        uint32_t lo1, hi1 = packsplit2(oa[nt][2] * inv1, oa[nt][3] * inv1, lo1);
        *(uint32_t*)((uint16_t*)oh + ob0 + nt * 8) = hi0;
        *(uint32_t*)((uint16_t*)ol + ob0 + nt * 8) = lo0;
        *(uint32_t*)((uint16_t*)oh + ob1 + nt * 8) = hi1;
        *(uint32_t*)((uint16_t*)ol + ob1 + nt * 8) = lo1;
    }
}

// -------- launch --------
extern "C" void kernel_launch(void* const* d_in, const int* in_sizes, int n_in,
                              void* d_out, int out_size) {
    const float* x    = (const float*)d_in[0];
    const float* cosb = (const float*)d_in[1];
    const float* sinb = (const float*)d_in[2];
    const int*   gm   = (const int*)d_in[4];
    const float* Wq   = (const float*)d_in[5];
    const float* bq   = (const float*)d_in[6];
    const float* Wqg  = (const float*)d_in[7];
    const float* bqg  = (const float*)d_in[8];
    const float* Wk   = (const float*)d_in[9];
    const float* bk   = (const float*)d_in[10];
    const float* Wkg  = (const float*)d_in[11];
    const float* bkg  = (const float*)d_in[12];
    const float* Wv   = (const float*)d_in[13];
    const float* bv   = (const float*)d_in[14];
    const float* Wvg  = (const float*)d_in[15];
    const float* bvg  = (const float*)d_in[16];
    const float* Wo   = (const float*)d_in[17];
    const float* Wog  = (const float*)d_in[18];
    const float* qw   = (const float*)d_in[19];
    const float* qwg  = (const float*)d_in[20];
    const float* kw   = (const float*)d_in[21];
    const float* kwg  = (const float*)d_in[22];
    float* out = (float*)d_out;

    void *pq, *pk, *po, *pxh, *pxl, *pkh, *pkl, *pvh, *pvl;
    cudaGetSymbolAddress(&pq, g_q);
    cudaGetSymbolAddress(&pk, g_k);
    cudaGetSymbolAddress(&po, g_o);
    cudaGetSymbolAddress(&pxh, g_xh);
    cudaGetSymbolAddress(&pxl, g_xl);
    cudaGetSymbolAddress(&pkh, g_kh);
    cudaGetSymbolAddress(&pkl, g_kl);
    cudaGetSymbolAddress(&pvh, g_vh);
    cudaGetSymbolAddress(&pvl, g_vl);
    float *qbuf = (float*)pq, *kbuf = (float*)pk;
    __nv_bfloat16 *xh = (__nv_bfloat16*)pxh, *xl = (__nv_bfloat16*)pxl;
    __nv_bfloat16* oh = (__nv_bfloat16*)po;
    __nv_bfloat16* ol = oh + (size_t)T_TOK * HIDDEN;

    cudaFuncSetAttribute(gemm_qkv, cudaFuncAttributeMaxDynamicSharedMemorySize,
                         GSMEM32);
    cudaFuncSetAttribute(gemm_o, cudaFuncAttributeMaxDynamicSharedMemorySize,
                         GSMEM32);
    cudaFuncSetAttribute(attn_mma, cudaFuncAttributeMaxDynamicSharedMemorySize,
                         A_SMEM);

    partition_kernel<<<1, 1024>>>(gm);

    cvt_perm<<<T_TOK * 512 / 256, 256>>>(x, xh, xl);
    cvt_weights<<<WROWS * 512 / 256, 256>>>(Wq, Wk, Wv, Wqg, Wkg, Wvg, Wo, Wog);

    gemm_qkv<<<dim3(NQKV / BN, ROWBLKS + 1), 256, GSMEM32>>>(
        xh, xl, bq, bqg, bk, bkg, bv, bvg,
        qbuf, kbuf, (__nv_bfloat16*)pvh, (__nv_bfloat16*)pvl);

    {
        int warps = T_TOK * (NH + NKV);
        rmsrope_kernel<<<(warps * 32 + 255) / 256, 256>>>(gm, cosb, sinb,
                                                          qw, qwg, kw, kwg);
    }

    attn_mma<<<(SEQ / 128) * NH * BATCH, 256, A_SMEM>>>(
        xh, xl, (__nv_bfloat16*)pkh, (__nv_bfloat16*)pkl,
        (__nv_bfloat16*)pvh, (__nv_bfloat16*)pvl, oh, ol);

    gemm_o<<<dim3(HIDDEN / BN, ROWBLKS + 1), 256, GSMEM32>>>(oh, ol, out);
}

// round 17
// speedup vs baseline: 1.1395x; 1.1395x over previous
#include <cuda_runtime.h>
#include <cuda_bf16.h>
#include <math.h>
#include <stdint.h>

#define T_TOK 8192
#define HIDDEN 2048
#define NH 16
#define NKV 4
#define HD 128
#define BATCH 8
#define SEQ 1024

#define BM 128
#define BN 64
#define BK 64
#define NCH (HIDDEN / BK)          // 32
#define ROWBLKS (T_TOK / BM)
#define NQKV 3072

// stage: Ah 16K | Al 16K | Bh 8K | Bl 8K = 48KB; 2 stages = 96KB; 2 CTA/SM
#define TA 16384
#define TB 8192
#define STG2 49152
#define GSMEM2 (2 * STG2)          // 98304

// -------- scratch --------
__device__ float g_q[(size_t)T_TOK * NH * HD];
__device__ float g_k[(size_t)T_TOK * NKV * HD];
__device__ float g_o[(size_t)T_TOK * NH * HD];   // reused as bf16 hi/lo planes
__device__ int   g_perm[T_TOK];
__device__ int   g_iperm[T_TOK];
__device__ int   g_n0;

__device__ __nv_bfloat16 g_xh[(size_t)T_TOK * HIDDEN];
__device__ __nv_bfloat16 g_xl[(size_t)T_TOK * HIDDEN];
__device__ __nv_bfloat16 g_kh[(size_t)T_TOK * NKV * HD];
__device__ __nv_bfloat16 g_kl[(size_t)T_TOK * NKV * HD];
__device__ __nv_bfloat16 g_vh[(size_t)T_TOK * NKV * HD];
__device__ __nv_bfloat16 g_vl[(size_t)T_TOK * NKV * HD];
#define WROWS (2 * NQKV + 2 * 2048)
__device__ __nv_bfloat16 g_wh[(size_t)WROWS * 2048];
__device__ __nv_bfloat16 g_wl[(size_t)WROWS * 2048];

// -------- asm helpers --------
__device__ __forceinline__ uint32_t smem_to_u32(const void* p) {
    uint32_t a;
    asm("{ .reg .u64 t; cvta.to.shared.u64 t, %1; cvt.u32.u64 %0, t; }"
        : "=r"(a) : "l"(p));
    return a;
}
#define CPA(dst, src) asm volatile( \
    "cp.async.cg.shared.global [%0], [%1], 16;" \
    :: "r"(dst), "l"(src) : "memory")
#define CPC() asm volatile("cp.async.commit_group;" ::: "memory")
#define CPW(n) asm volatile("cp.async.wait_group %0;" :: "n"(n) : "memory")

#define LDSM4(r, a) asm volatile( \
    "ldmatrix.sync.aligned.m8n8.x4.shared.b16 {%0,%1,%2,%3}, [%4];" \
    : "=r"((r)[0]), "=r"((r)[1]), "=r"((r)[2]), "=r"((r)[3]) : "r"(a))
#define LDSM4T(r, a) asm volatile( \
    "ldmatrix.sync.aligned.m8n8.x4.trans.shared.b16 {%0,%1,%2,%3}, [%4];" \
    : "=r"((r)[0]), "=r"((r)[1]), "=r"((r)[2]), "=r"((r)[3]) : "r"(a))

#define MMA_BF16(d, a, b0, b1) asm volatile( \
    "mma.sync.aligned.m16n8k16.row.col.f32.bf16.bf16.f32 " \
    "{%0,%1,%2,%3}, {%4,%5,%6,%7}, {%8,%9}, {%0,%1,%2,%3};" \
    : "+f"((d)[0]), "+f"((d)[1]), "+f"((d)[2]), "+f"((d)[3]) \
    : "r"((a)[0]), "r"((a)[1]), "r"((a)[2]), "r"((a)[3]), "r"(b0), "r"(b1))

// -------- partition --------
__global__ void partition_kernel(const int* __restrict__ gm) {
    __shared__ int sc[1024];
    int tid = threadIdx.x, base = tid * 8, z = 0;
#pragma unroll
    for (int i = 0; i < 8; i++) z += (gm[base + i] > 0) ? 0 : 1;
    sc[tid] = z;
    __syncthreads();
    for (int off = 1; off < 1024; off <<= 1) {
        int v = (tid >= off) ? sc[tid - off] : 0;
        __syncthreads();
        sc[tid] += v;
        __syncthreads();
    }
    int total0 = sc[1023], zpos = sc[tid] - z, opos = base - zpos;
#pragma unroll
    for (int i = 0; i < 8; i++) {
        int t = base + i;
        if (gm[t] > 0) {
            int p = total0 + opos++;
            g_perm[p] = t;
            g_iperm[t] = p;
        } else {
            int p = zpos++;
            g_perm[p] = t;
            g_iperm[t] = p;
        }
    }
    if (tid == 0) g_n0 = total0;
}

// -------- fp32 -> bf16 hi/lo split --------
__device__ __forceinline__ void split4(float4 v, uint2& H, uint2& L) {
    __nv_bfloat16 h0 = __float2bfloat16(v.x), h1 = __float2bfloat16(v.y);
    __nv_bfloat16 h2 = __float2bfloat16(v.z), h3 = __float2bfloat16(v.w);
    __nv_bfloat16 l0 = __float2bfloat16(v.x - __bfloat162float(h0));
    __nv_bfloat16 l1 = __float2bfloat16(v.y - __bfloat162float(h1));
    __nv_bfloat16 l2 = __float2bfloat16(v.z - __bfloat162float(h2));
    __nv_bfloat16 l3 = __float2bfloat16(v.w - __bfloat162float(h3));
    H.x = ((uint32_t)__bfloat16_as_ushort(h1) << 16) | __bfloat16_as_ushort(h0);
    H.y = ((uint32_t)__bfloat16_as_ushort(h3) << 16) | __bfloat16_as_ushort(h2);
    L.x = ((uint32_t)__bfloat16_as_ushort(l1) << 16) | __bfloat16_as_ushort(l0);
    L.y = ((uint32_t)__bfloat16_as_ushort(l3) << 16) | __bfloat16_as_ushort(l2);
}
__device__ __forceinline__ uint32_t packsplit2(float x, float y, uint32_t& lo) {
    __nv_bfloat16 hx = __float2bfloat16(x), hy = __float2bfloat16(y);
    __nv_bfloat16 lx = __float2bfloat16(x - __bfloat162float(hx));
    __nv_bfloat16 ly = __float2bfloat16(y - __bfloat162float(hy));
    lo = ((uint32_t)__bfloat16_as_ushort(ly) << 16) | __bfloat16_as_ushort(lx);
    return ((uint32_t)__bfloat16_as_ushort(hy) << 16) | __bfloat16_as_ushort(hx);
}
__global__ void cvt_perm(const float* __restrict__ src,
                         __nv_bfloat16* __restrict__ hi,
                         __nv_bfloat16* __restrict__ lo) {
    int i = blockIdx.x * 256 + threadIdx.x;
    int r = i >> 9, c4 = i & 511;
    float4 v = ((const float4*)(src + (size_t)g_perm[r] * HIDDEN))[c4];
    uint2 H, L;
    split4(v, H, L);
    ((uint2*)hi)[i] = H;
    ((uint2*)lo)[i] = L;
}
__global__ void cvt_weights(const float* __restrict__ Wq_,
                            const float* __restrict__ Wk_,
                            const float* __restrict__ Wv_,
                            const float* __restrict__ Wqg_,
                            const float* __restrict__ Wkg_,
                            const float* __restrict__ Wvg_,
                            const float* __restrict__ Wo_,
                            const float* __restrict__ Wog_) {
    int i = blockIdx.x * 256 + threadIdx.x;
    int r = i >> 9, c4 = i & 511;
    const float* src;
    if (r < 2048)       src = Wq_  + (size_t)r * 2048;
    else if (r < 2560)  src = Wk_  + (size_t)(r - 2048) * 2048;
    else if (r < 3072)  src = Wv_  + (size_t)(r - 2560) * 2048;
    else if (r < 5120)  src = Wqg_ + (size_t)(r - 3072) * 2048;
    else if (r < 5632)  src = Wkg_ + (size_t)(r - 5120) * 2048;
    else if (r < 6144)  src = Wvg_ + (size_t)(r - 5632) * 2048;
    else if (r < 8192)  src = Wo_  + (size_t)(r - 6144) * 2048;
    else                src = Wog_ + (size_t)(r - 8192) * 2048;
    float4 v = ((const float4*)src)[c4];
    uint2 H, L;
    split4(v, H, L);
    ((uint2*)g_wh)[i] = H;
    ((uint2*)g_wl)[i] = L;
}

// =================================================================
// bf16 GEMM mainloop: CTA 128x64, BK=64, warp 32x32 (4m x 2n),
// 2-stage cp.async ping-pong, 2 CTAs/SM. 128B-row swizzle (proven).
// =================================================================
#define GEMM_MAIN(AghP, AglP, BhP, BlP)                                    \
    float acc[2][4][4];                                                    \
    _Pragma("unroll")                                                      \
    for (int a = 0; a < 2; a++)                                            \
        _Pragma("unroll")                                                  \
        for (int b = 0; b < 4; b++)                                        \
            _Pragma("unroll")                                              \
            for (int c = 0; c < 4; c++) acc[a][b][c] = 0.0f;               \
    const int tid = threadIdx.x, wid = tid >> 5, lane = tid & 31;          \
    const int mbase = (wid & 3) * 32;                                      \
    const int nbase = (wid >> 2) * 32;                                     \
    extern __shared__ char smem[];                                         \
    const uint32_t sb = smem_to_u32(smem);                                 \
    const int ldrow = tid >> 3, ldc = tid & 7;                             \
    auto load_stage = [&](int st, int ch_) {                               \
        uint32_t base_ = sb + st * STG2;                                   \
        int k0 = ch_ * BK;                                                 \
        _Pragma("unroll")                                                  \
        for (int it = 0; it < 4; it++) {                                   \
            int row = ldrow + it * 32;                                     \
            uint32_t d = base_ + row * 128 + ((ldc ^ (row & 7)) << 4);     \
            size_t ga = (size_t)(row0 + row) * HIDDEN + k0 + ldc * 8;      \
            CPA(d,      AghP + ga);                                        \
            CPA(d + TA, AglP + ga);                                        \
        }                                                                  \
        _Pragma("unroll")                                                  \
        for (int it = 0; it < 2; it++) {                                   \
            int row = ldrow + it * 32;                                     \
            uint32_t d = base_ + 2 * TA + row * 128 +                      \
                         ((ldc ^ (row & 7)) << 4);                         \
            size_t gb = (size_t)(col0 + row) * HIDDEN + k0 + ldc * 8;      \
            CPA(d,      BhP + gb);                                         \
            CPA(d + TB, BlP + gb);                                         \
        }                                                                  \
        CPC();                                                             \
    };                                                                     \
    load_stage(0, 0);                                                      \
    const int q_ = lane >> 3, rr = lane & 7;                               \
    const int arow_off = (q_ & 1) * 8 + rr;                                \
    const int achk_off = (q_ >> 1);                                        \
    const int brow_off = (q_ >> 1) * 8 + rr;                               \
    const int bchk_off = (q_ & 1);                                         \
    for (int ch = 0; ch < NCH; ch++) {                                     \
        CPW(0);                                                            \
        __syncthreads();                                                   \
        if (ch + 1 < NCH) load_stage((ch + 1) & 1, ch + 1);                \
        const uint32_t so = sb + (ch & 1) * STG2;                          \
        _Pragma("unroll")                                                  \
        for (int ks = 0; ks < 4; ks++) {                                   \
            uint32_t bh[2][4], bl[2][4];                                   \
            _Pragma("unroll")                                              \
            for (int nb = 0; nb < 2; nb++) {                               \
                int row = nbase + nb * 16 + brow_off;                      \
                int chk = ks * 2 + bchk_off;                               \
                uint32_t bd = so + 2 * TA + row * 128 +                    \
                              ((chk ^ (row & 7)) << 4);                    \
                LDSM4(bh[nb], bd);                                         \
                LDSM4(bl[nb], bd + TB);                                    \
            }                                                              \
            _Pragma("unroll")                                              \
            for (int mt = 0; mt < 2; mt++) {                               \
                uint32_t ah4[4], al4[4];                                   \
                int row = mbase + mt * 16 + arow_off;                      \
                int chk = ks * 2 + achk_off;                               \
                uint32_t ad = so + row * 128 + ((chk ^ (row & 7)) << 4);   \
                LDSM4(ah4, ad);                                            \
                LDSM4(al4, ad + TA);                                       \
                _Pragma("unroll")                                          \
                for (int nt = 0; nt < 4; nt++) {                           \
                    int nb = nt >> 1, i0 = (nt & 1) * 2;                   \
                    MMA_BF16(acc[mt][nt], ah4, bh[nb][i0], bh[nb][i0+1]);  \
                    MMA_BF16(acc[mt][nt], ah4, bl[nb][i0], bl[nb][i0+1]);  \
                    MMA_BF16(acc[mt][nt], al4, bh[nb][i0], bh[nb][i0+1]);  \
                }                                                          \
            }                                                              \
        }                                                                  \
        __syncthreads();                                                   \
    }

__device__ __forceinline__ bool route_setup(int by, int n0,
                                            int& rowblk, int& wlo, int& whi,
                                            bool& useW1) {
    if (by < ROWBLKS) {
        rowblk = by;
        int lo = rowblk * BM, hi2 = lo + BM;
        if (hi2 <= n0)     { useW1 = false; wlo = lo; whi = hi2; }
        else if (lo >= n0) { useW1 = true;  wlo = lo; whi = hi2; }
        else               { useW1 = false; wlo = lo; whi = n0;  }
        return true;
    }
    if ((n0 & (BM - 1)) == 0) return false;
    rowblk = n0 / BM; useW1 = true; wlo = n0; whi = rowblk * BM + BM;
    return true;
}

// =================================================================
// merged QKV GEMM: segmented epilogue
// =================================================================
__global__ __launch_bounds__(256, 2)
void gemm_qkv(const __nv_bfloat16* __restrict__ Agh,
              const __nv_bfloat16* __restrict__ Agl,
              const float* __restrict__ bq, const float* __restrict__ bqg,
              const float* __restrict__ bk, const float* __restrict__ bkg,
              const float* __restrict__ bv, const float* __restrict__ bvg,
              float* __restrict__ Cq, float* __restrict__ Ck,
              __nv_bfloat16* __restrict__ Vh, __nv_bfloat16* __restrict__ Vl) {
    const int n0 = g_n0;
    int rowblk, wlo, whi;
    bool useW1;
    if (!route_setup(blockIdx.y, n0, rowblk, wlo, whi, useW1)) return;
    const int row0 = rowblk * BM;
    const int col0 = blockIdx.x * BN;
    const __nv_bfloat16* __restrict__ Bh = g_wh + (useW1 ? (size_t)NQKV * 2048 : 0);
    const __nv_bfloat16* __restrict__ Bl = g_wl + (useW1 ? (size_t)NQKV * 2048 : 0);

    GEMM_MAIN(Agh, Agl, Bh, Bl)

    const int seg = (col0 < 2048) ? 0 : (col0 < 2560 ? 1 : 2);
    const float* bias;
    int cbase, Nout;
    if (seg == 0)      { bias = useW1 ? bqg : bq; cbase = col0;        Nout = 2048; }
    else if (seg == 1) { bias = useW1 ? bkg : bk; cbase = col0 - 2048; Nout = 512; }
    else               { bias = useW1 ? bvg : bv; cbase = col0 - 2560; Nout = 512; }

#pragma unroll
    for (int mt = 0; mt < 2; mt++) {
        int r0 = row0 + mbase + mt * 16 + (lane >> 2);
        int r1 = r0 + 8;
        bool w0 = (r0 >= wlo) && (r0 < whi);
        bool w1 = (r1 >= wlo) && (r1 < whi);
        int tok0 = w0 ? g_perm[r0] : 0;
        int tok1 = w1 ? g_perm[r1] : 0;
#pragma unroll
        for (int nt = 0; nt < 4; nt++) {
            int colL = cbase + nbase + nt * 8 + (lane & 3) * 2;
            float b0f = bias[colL], b1f = bias[colL + 1];
            float v00 = acc[mt][nt][0] + b0f, v01 = acc[mt][nt][1] + b1f;
            float v10 = acc[mt][nt][2] + b0f, v11 = acc[mt][nt][3] + b1f;
            if (seg < 2) {
                float* C = (seg == 0) ? Cq : Ck;
                if (w0) *(float2*)(C + (size_t)tok0 * Nout + colL) = make_float2(v00, v01);
                if (w1) *(float2*)(C + (size_t)tok1 * Nout + colL) = make_float2(v10, v11);
            } else {
                if (w0) {
                    uint32_t lo_, hi_ = packsplit2(v00, v01, lo_);
                    *(uint32_t*)((uint16_t*)Vh + (size_t)tok0 * 512 + colL) = hi_;
                    *(uint32_t*)((uint16_t*)Vl + (size_t)tok0 * 512 + colL) = lo_;
                }
                if (w1) {
                    uint32_t lo_, hi_ = packsplit2(v10, v11, lo_);
                    *(uint32_t*)((uint16_t*)Vh + (size_t)tok1 * 512 + colL) = hi_;
                    *(uint32_t*)((uint16_t*)Vl + (size_t)tok1 * 512 + colL) = lo_;
                }
            }
        }
    }
}

// =================================================================
// O-projection GEMM -> fp32 out, no bias
// =================================================================
__global__ __launch_bounds__(256, 2)
void gemm_o(const __nv_bfloat16* __restrict__ Agh,
            const __nv_bfloat16* __restrict__ Agl,
            float* __restrict__ C) {
    const int n0 = g_n0;
    int rowblk, wlo, whi;
    bool useW1;
    if (!route_setup(blockIdx.y, n0, rowblk, wlo, whi, useW1)) return;
    const int row0 = rowblk * BM;
    const int col0 = blockIdx.x * BN;
    const size_t wbase = (size_t)(2 * NQKV) * 2048 +
                         (useW1 ? (size_t)2048 * 2048 : 0);
    const __nv_bfloat16* __restrict__ Bh = g_wh + wbase;
    const __nv_bfloat16* __restrict__ Bl = g_wl + wbase;

    GEMM_MAIN(Agh, Agl, Bh, Bl)

#pragma unroll
    for (int mt = 0; mt < 2; mt++) {
        int r0 = row0 + mbase + mt * 16 + (lane >> 2);
        int r1 = r0 + 8;
        bool w0 = (r0 >= wlo) && (r0 < whi);
        bool w1 = (r1 >= wlo) && (r1 < whi);
        int tok0 = w0 ? g_perm[r0] : 0;
        int tok1 = w1 ? g_perm[r1] : 0;
#pragma unroll
        for (int nt = 0; nt < 4; nt++) {
            int colg = col0 + nbase + nt * 8 + (lane & 3) * 2;
            if (w0)
                *(float2*)(C + (size_t)tok0 * HIDDEN + colg) =
                    make_float2(acc[mt][nt][0], acc[mt][nt][1]);
            if (w1)
                *(float2*)(C + (size_t)tok1 * HIDDEN + colg) =
                    make_float2(acc[mt][nt][2], acc[mt][nt][3]);
        }
    }
}

// =================================================================
// RMS norm + RoPE; emits bf16 hi/lo (Q pre-scaled by 1/sqrt(D))
// =================================================================
__global__ void rmsrope_kernel(const int* __restrict__ gm,
                               const float* __restrict__ cosb,
                               const float* __restrict__ sinb,
                               const float* __restrict__ qw,
                               const float* __restrict__ qwg,
                               const float* __restrict__ kw,
                               const float* __restrict__ kwg) {
    const int warp = (blockIdx.x * blockDim.x + threadIdx.x) >> 5;
    const int lane = threadIdx.x & 31;
    const int QP = T_TOK * NH;
    if (warp >= QP + T_TOK * NKV) return;
    const float* src;
    __nv_bfloat16 *dh, *dl;
    const float* w;
    int t;
    float oscale;
    if (warp < QP) {
        t = warp >> 4;
        src = g_q + (size_t)warp * HD;
        dh = g_xh + (size_t)warp * HD;
        dl = g_xl + (size_t)warp * HD;
        w = (gm[t] > 0) ? qwg : qw;
        oscale = 0.08838834764831845f;
    } else {
        int p = warp - QP;
        t = p >> 2;
        src = g_k + (size_t)p * HD;
        dh = g_kh + (size_t)p * HD;
        dl = g_kl + (size_t)p * HD;
        w = (gm[t] > 0) ? kwg : kw;
        oscale = 1.0f;
    }
    float v[4];
#pragma unroll
    for (int r = 0; r < 4; r++) v[r] = src[lane + 32 * r];
    float ss = v[0]*v[0] + v[1]*v[1] + v[2]*v[2] + v[3]*v[3];
#pragma unroll
    for (int off = 16; off > 0; off >>= 1)
        ss += __shfl_xor_sync(0xffffffffu, ss, off);
    float rs = rsqrtf(ss * (1.0f / 128.0f) + 1e-6f);
#pragma unroll
    for (int r = 0; r < 4; r++) v[r] = v[r] * rs * w[lane + 32 * r];
    float rot[4] = {-v[2], -v[3], v[0], v[1]};
#pragma unroll
    for (int r = 0; r < 4; r++) {
        int d = lane + 32 * r;
        float c = cosb[(size_t)t * HD + d];
        float s = sinb[(size_t)t * HD + d];
        float val = (v[r] * c + rot[r] * s) * oscale;
        __nv_bfloat16 h = __float2bfloat16(val);
        __nv_bfloat16 l = __float2bfloat16(val - __bfloat162float(h));
        dh[d] = h;
        dl[d] = l;
    }
}

// =================================================================
// FA2 attention (bf16 3-term), LPT grid, fused permuted bf16 epilogue
// =================================================================
#define A_RGN 65536
#define A_SMEM (3 * A_RGN)

__device__ __forceinline__ void load_kv_stage(
    uint32_t rgn, int tid,
    const __nv_bfloat16* __restrict__ kh, const __nv_bfloat16* __restrict__ kl,
    const __nv_bfloat16* __restrict__ vh, const __nv_bfloat16* __restrict__ vl,
    size_t gbase) {
#pragma unroll
    for (int i = 0; i < 4; i++) {
        int idx = tid + (i << 8);
        int row = idx >> 4, c = idx & 15;
        uint32_t d = rgn + row * 256 + ((c ^ (row & 7)) << 4);
        size_t g = gbase + (size_t)row * 512 + c * 8;
        CPA(d,          kh + g);
        CPA(d + 16384,  kl + g);
        CPA(d + 32768,  vh + g);
        CPA(d + 49152,  vl + g);
    }
    CPC();
}

__global__ __launch_bounds__(256, 1)
void attn_mma(const __nv_bfloat16* __restrict__ qh,
              const __nv_bfloat16* __restrict__ ql,
              const __nv_bfloat16* __restrict__ kh,
              const __nv_bfloat16* __restrict__ kl,
              const __nv_bfloat16* __restrict__ vh,
              const __nv_bfloat16* __restrict__ vl,
              __nv_bfloat16* __restrict__ oh,
              __nv_bfloat16* __restrict__ ol) {
    extern __shared__ char smem[];
    const uint32_t sb = smem_to_u32(smem);
    const int tid = threadIdx.x, wid = tid >> 5, lane = tid & 31;
    const int bid = blockIdx.x;
    const int qb = (SEQ / 128 - 1) - (bid >> 7);
    const int hb = bid & 127;
    const int h = hb & 15;
    const int b = hb >> 4;
    const int kvh = h >> 2;
    const int q0 = qb * 128;
    const size_t qgbase = ((size_t)(b * SEQ + q0)) * 2048 + h * 128;
    const size_t kvgbase = ((size_t)(b * SEQ)) * 512 + kvh * 128;
    const int nkb = 2 * qb + 2;

#pragma unroll
    for (int i = 0; i < 8; i++) {
        int idx = tid + (i << 8);
        int row = idx >> 4, c = idx & 15;
        uint32_t d = sb + row * 256 + ((c ^ (row & 7)) << 4);
        size_t g = qgbase + (size_t)row * 2048 + c * 8;
        CPA(d, qh + g);
        CPA(d + 32768, ql + g);
    }
    CPC();
    load_kv_stage(sb + A_RGN, tid, kh, kl, vh, vl, kvgbase);
    CPW(1);
    __syncthreads();

    const int rr = lane & 7;
    const int arow = wid * 16 + ((lane >> 3) & 1) * 8 + rr;
    const int acb = lane >> 4;
    uint32_t Qh4[8][4], Ql4[8][4];
#pragma unroll
    for (int kk = 0; kk < 8; kk++) {
        int ck = kk * 2 + acb;
        uint32_t ad = sb + arow * 256 + ((ck ^ (arow & 7)) << 4);
        LDSM4(Qh4[kk], ad);
        LDSM4(Ql4[kk], ad + 32768);
    }
    __syncthreads();
    if (nkb > 1)
        load_kv_stage(sb + 2 * A_RGN, tid, kh, kl, vh, vl, kvgbase + 64 * 512);

    float m0 = -1e30f, m1 = -1e30f, l0 = 0.0f, l1 = 0.0f;
    float oa[16][4];
#pragma unroll
    for (int i = 0; i < 16; i++)
#pragma unroll
        for (int j = 0; j < 4; j++) oa[i][j] = 0.0f;

    const int brow_off = ((lane >> 4) & 1) * 8 + rr;
    const int bcb = (lane >> 3) & 1;
    const int vrow_off = lane & 15;
    const int vcb = lane >> 4;
    const int rowg0 = q0 + wid * 16 + (lane >> 2);
    const int rowg1 = rowg0 + 8;
    const int warprow0 = q0 + wid * 16;

    for (int kb = 0; kb < nkb; kb++) {
        if (kb + 1 == nkb) CPW(0); else CPW(1);
        __syncthreads();
        if (kb + 2 < nkb)
            load_kv_stage(sb + ((kb + 3) % 3) * A_RGN, tid, kh, kl, vh, vl,
                          kvgbase + (size_t)(kb + 2) * 64 * 512);

        const uint32_t so = sb + ((kb + 1) % 3) * A_RGN;

        float s[8][4];
#pragma unroll
        for (int i = 0; i < 8; i++)
#pragma unroll
            for (int j = 0; j < 4; j++) s[i][j] = 0.0f;

#pragma unroll
        for (int kk = 0; kk < 8; kk++) {
#pragma unroll
            for (int p = 0; p < 4; p++) {
                int krow = p * 16 + brow_off;
                int ck = kk * 2 + bcb;
                uint32_t kd = so + krow * 256 + ((ck ^ (krow & 7)) << 4);
                uint32_t bh4[4], bl4[4];
                LDSM4(bh4, kd);
                LDSM4(bl4, kd + 16384);
                MMA_BF16(s[2*p],   Qh4[kk], bh4[0], bh4[1]);
                MMA_BF16(s[2*p],   Qh4[kk], bl4[0], bl4[1]);
                MMA_BF16(s[2*p],   Ql4[kk], bh4[0], bh4[1]);
                MMA_BF16(s[2*p+1], Qh4[kk], bh4[2], bh4[3]);
                MMA_BF16(s[2*p+1], Qh4[kk], bl4[2], bl4[3]);
                MMA_BF16(s[2*p+1], Ql4[kk], bh4[2], bh4[3]);
            }
        }

        if (kb * 64 + 63 > warprow0) {
            int colb = kb * 64 + (lane & 3) * 2;
#pragma unroll
            for (int nt = 0; nt < 8; nt++) {
                int c = colb + nt * 8;
                if (c > rowg0)     s[nt][0] = -1e30f;
                if (c + 1 > rowg0) s[nt][1] = -1e30f;
                if (c > rowg1)     s[nt][2] = -1e30f;
                if (c + 1 > rowg1) s[nt][3] = -1e30f;
            }
        }

        float mx0 = -1e30f, mx1 = -1e30f;
#pragma unroll
        for (int nt = 0; nt < 8; nt++) {
            mx0 = fmaxf(mx0, fmaxf(s[nt][0], s[nt][1]));
            mx1 = fmaxf(mx1, fmaxf(s[nt][2], s[nt][3]));
        }
        mx0 = fmaxf(mx0, __shfl_xor_sync(0xffffffffu, mx0, 1));
        mx0 = fmaxf(mx0, __shfl_xor_sync(0xffffffffu, mx0, 2));
        mx1 = fmaxf(mx1, __shfl_xor_sync(0xffffffffu, mx1, 1));
        mx1 = fmaxf(mx1, __shfl_xor_sync(0xffffffffu, mx1, 2));
        float nm0 = fmaxf(m0, mx0), nm1 = fmaxf(m1, mx1);
        float corr0 = __expf(m0 - nm0), corr1 = __expf(m1 - nm1);
        float ps0 = 0.0f, ps1 = 0.0f;
#pragma unroll
        for (int nt = 0; nt < 8; nt++) {
            s[nt][0] = __expf(s[nt][0] - nm0);
            s[nt][1] = __expf(s[nt][1] - nm0);
            s[nt][2] = __expf(s[nt][2] - nm1);
            s[nt][3] = __expf(s[nt][3] - nm1);
            ps0 += s[nt][0] + s[nt][1];
            ps1 += s[nt][2] + s[nt][3];
        }
        ps0 += __shfl_xor_sync(0xffffffffu, ps0, 1);
        ps0 += __shfl_xor_sync(0xffffffffu, ps0, 2);
        ps1 += __shfl_xor_sync(0xffffffffu, ps1, 1);
        ps1 += __shfl_xor_sync(0xffffffffu, ps1, 2);
        l0 = l0 * corr0 + ps0;
        l1 = l1 * corr1 + ps1;
        m0 = nm0; m1 = nm1;
#pragma unroll
        for (int i = 0; i < 16; i++) {
            oa[i][0] *= corr0; oa[i][1] *= corr0;
            oa[i][2] *= corr1; oa[i][3] *= corr1;
        }

#pragma unroll
        for (int kt = 0; kt < 4; kt++) {
            uint32_t ah4[4], al4[4];
            ah4[0] = packsplit2(s[2*kt][0],   s[2*kt][1],   al4[0]);
            ah4[1] = packsplit2(s[2*kt][2],   s[2*kt][3],   al4[1]);
            ah4[2] = packsplit2(s[2*kt+1][0], s[2*kt+1][1], al4[2]);
            ah4[3] = packsplit2(s[2*kt+1][2], s[2*kt+1][3], al4[3]);
#pragma unroll
            for (int dp = 0; dp < 8; dp++) {
                int vr = kt * 16 + vrow_off;
                int ck = dp * 2 + vcb;
                uint32_t vd = so + 32768 + vr * 256 + ((ck ^ (vr & 7)) << 4);
                uint32_t bh4[4], bl4[4];
                LDSM4T(bh4, vd);
                LDSM4T(bl4, vd + 16384);
                MMA_BF16(oa[2*dp],   ah4, bh4[0], bh4[1]);
                MMA_BF16(oa[2*dp],   ah4, bl4[0], bl4[1]);
                MMA_BF16(oa[2*dp],   al4, bh4[0], bh4[1]);
                MMA_BF16(oa[2*dp+1], ah4, bh4[2], bh4[3]);
                MMA_BF16(oa[2*dp+1], ah4, bl4[2], bl4[3]);
                MMA_BF16(oa[2*dp+1], al4, bh4[2], bh4[3]);
            }
        }
    }

    float inv0 = 1.0f / l0, inv1 = 1.0f / l1;
    int p0 = g_iperm[b * SEQ + rowg0];
    int p1 = g_iperm[b * SEQ + rowg1];
    size_t ob0 = (size_t)p0 * 2048 + h * 128 + (lane & 3) * 2;
    size_t ob1 = (size_t)p1 * 2048 + h * 128 + (lane & 3) * 2;
#pragma unroll
    for (int nt = 0; nt < 16; nt++) {
        uint32_t lo0, hi0 = packsplit2(oa[nt][0] * inv0, oa[nt][1] * inv0, lo0);
        uint32_t lo1, hi1 = packsplit2(oa[nt][2] * inv1, oa[nt][3] * inv1, lo1);
        *(uint32_t*)((uint16_t*)oh + ob0 + nt * 8) = hi0;
        *(uint32_t*)((uint16_t*)ol + ob0 + nt * 8) = lo0;
        *(uint32_t*)((uint16_t*)oh + ob1 + nt * 8) = hi1;
        *(uint32_t*)((uint16_t*)ol + ob1 + nt * 8) = lo1;
    }
}

// -------- launch --------
extern "C" void kernel_launch(void* const* d_in, const int* in_sizes, int n_in,
                              void* d_out, int out_size) {
    const float* x    = (const float*)d_in[0];
    const float* cosb = (const float*)d_in[1];
    const float* sinb = (const float*)d_in[2];
    const int*   gm   = (const int*)d_in[4];
    const float* Wq   = (const float*)d_in[5];
    const float* bq   = (const float*)d_in[6];
    const float* Wqg  = (const float*)d_in[7];
    const float* bqg  = (const float*)d_in[8];
    const float* Wk   = (const float*)d_in[9];
    const float* bk   = (const float*)d_in[10];
    const float* Wkg  = (const float*)d_in[11];
    const float* bkg  = (const float*)d_in[12];
    const float* Wv   = (const float*)d_in[13];
    const float* bv   = (const float*)d_in[14];
    const float* Wvg  = (const float*)d_in[15];
    const float* bvg  = (const float*)d_in[16];
    const float* Wo   = (const float*)d_in[17];
    const float* Wog  = (const float*)d_in[18];
    const float* qw   = (const float*)d_in[19];
    const float* qwg  = (const float*)d_in[20];
    const float* kw   = (const float*)d_in[21];
    const float* kwg  = (const float*)d_in[22];
    float* out = (float*)d_out;

    void *pq, *pk, *po, *pxh, *pxl, *pkh, *pkl, *pvh, *pvl;
    cudaGetSymbolAddress(&pq, g_q);
    cudaGetSymbolAddress(&pk, g_k);
    cudaGetSymbolAddress(&po, g_o);
    cudaGetSymbolAddress(&pxh, g_xh);
    cudaGetSymbolAddress(&pxl, g_xl);
    cudaGetSymbolAddress(&pkh, g_kh);
    cudaGetSymbolAddress(&pkl, g_kl);
    cudaGetSymbolAddress(&pvh, g_vh);
    cudaGetSymbolAddress(&pvl, g_vl);
    float *qbuf = (float*)pq, *kbuf = (float*)pk;
    __nv_bfloat16 *xh = (__nv_bfloat16*)pxh, *xl = (__nv_bfloat16*)pxl;
    __nv_bfloat16* oh = (__nv_bfloat16*)po;
    __nv_bfloat16* ol = oh + (size_t)T_TOK * HIDDEN;

    cudaFuncSetAttribute(gemm_qkv, cudaFuncAttributeMaxDynamicSharedMemorySize,
                         GSMEM2);
    cudaFuncSetAttribute(gemm_o, cudaFuncAttributeMaxDynamicSharedMemorySize,
                         GSMEM2);
    cudaFuncSetAttribute(attn_mma, cudaFuncAttributeMaxDynamicSharedMemorySize,
                         A_SMEM);

    partition_kernel<<<1, 1024>>>(gm);

    cvt_perm<<<T_TOK * 512 / 256, 256>>>(x, xh, xl);
    cvt_weights<<<WROWS * 512 / 256, 256>>>(Wq, Wk, Wv, Wqg, Wkg, Wvg, Wo, Wog);

    gemm_qkv<<<dim3(NQKV / BN, ROWBLKS + 1), 256, GSMEM2>>>(
        xh, xl, bq, bqg, bk, bkg, bv, bvg,
        qbuf, kbuf, (__nv_bfloat16*)pvh, (__nv_bfloat16*)pvl);

    {
        int warps = T_TOK * (NH + NKV);
        rmsrope_kernel<<<(warps * 32 + 255) / 256, 256>>>(gm, cosb, sinb,
                                                          qw, qwg, kw, kwg);
    }

    attn_mma<<<(SEQ / 128) * NH * BATCH, 256, A_SMEM>>>(
        xh, xl, (__nv_bfloat16*)pkh, (__nv_bfloat16*)pkl,
        (__nv_bfloat16*)pvh, (__nv_bfloat16*)pvl, oh, ol);

    gemm_o<<<dim3(HIDDEN / BN, ROWBLKS + 1), 256, GSMEM2>>>(oh, ol, out);
}